// round 1
// baseline (speedup 1.0000x reference)
#include <cuda_runtime.h>
#include <cuda_bf16.h>
#include <cstdint>

// Problem constants (fixed by the reference)
#define NNODES 50000
#define NREL   8
#define DIM    128
#define NEDGES 800000

// ---------------- scratch (static device globals; no allocation) ----------------
__device__ float g_Y[(size_t)NREL * NNODES * DIM];   // per-relation transformed features (204.8 MB)
__device__ float g_h1[(size_t)NNODES * DIM];         // layer1 accumulator / relu output
__device__ float g_h2[(size_t)NNODES * DIM];         // layer2 accumulator
__device__ float g_inv[NREL * NNODES];               // 1/max(cnt,1)
__device__ int   g_cnt[NREL * NNODES];

// ---------------- small helpers ----------------
__device__ __forceinline__ unsigned long long pack2(float a) {
    unsigned long long r;
    asm("mov.b64 %0, {%1, %1};" : "=l"(r) : "f"(a));
    return r;
}
__device__ __forceinline__ void fma2(unsigned long long& d, unsigned long long a, unsigned long long b) {
    asm("fma.rn.f32x2 %0, %1, %2, %0;" : "+l"(d) : "l"(a), "l"(b));
}
__device__ __forceinline__ void unpack2(unsigned long long v, float& lo, float& hi) {
    asm("mov.b64 {%0, %1}, %2;" : "=f"(lo), "=f"(hi) : "l"(v));
}

// ---------------- setup kernels ----------------
__global__ void k_zero_cnt(int* __restrict__ cnt, int n) {
    int i = blockIdx.x * blockDim.x + threadIdx.x;
    if (i < n) cnt[i] = 0;
}

__global__ void k_count(const int* __restrict__ r, const int* __restrict__ t,
                        int* __restrict__ cnt, int E) {
    int e = blockIdx.x * blockDim.x + threadIdx.x;
    if (e < E) atomicAdd(&cnt[r[e] * NNODES + t[e]], 1);
}

__global__ void k_invert(const int* __restrict__ cnt, float* __restrict__ inv, int n) {
    int i = blockIdx.x * blockDim.x + threadIdx.x;
    if (i < n) inv[i] = 1.0f / fmaxf((float)cnt[i], 1.0f);
}

// ---------------- GEMM: Y_z = X @ B_z for z in [0,9), z==8 is root path (+bias) ----------------
// Tile: BM=64 rows x BN=128 cols, BK=32. 256 threads, each computes 4 rows x 8 cols
// as 16 packed f32x2 accumulators via fma.rn.f32x2 (2x fp32 FMA rate).
__global__ __launch_bounds__(256) void k_gemm9(
    const float* __restrict__ X, const float* __restrict__ Wrel,
    const float* __restrict__ root, const float* __restrict__ bias,
    float* __restrict__ Y, float* __restrict__ acc, int Nn)
{
    const int z = blockIdx.z;
    const float* Bm = (z < 8) ? (Wrel + (size_t)z * DIM * DIM) : root;
    float* C = (z < 8) ? (Y + (size_t)z * Nn * DIM) : acc;

    __shared__ float As[64][33];     // padded: conflict-free column reads
    __shared__ float Bs[32][128];

    const int tid = threadIdx.x;
    const int ty = tid >> 4;         // 0..15 -> rows ty*4 .. ty*4+3
    const int tx = tid & 15;         // cols tx*2 + j*32, j=0..3
    const int row0 = blockIdx.x * 64;

    unsigned long long c2[4][4];
#pragma unroll
    for (int i = 0; i < 4; i++)
#pragma unroll
        for (int j = 0; j < 4; j++) c2[i][j] = 0ull;

    for (int k0 = 0; k0 < DIM; k0 += 32) {
        // load A tile 64x32 (scalar, coalesced)
#pragma unroll
        for (int l = 0; l < 8; l++) {
            int idx = tid + l * 256;
            int rr = idx >> 5, cc = idx & 31;
            int gr = row0 + rr;
            As[rr][cc] = (gr < Nn) ? X[(size_t)gr * DIM + k0 + cc] : 0.0f;
        }
        // load B tile 32x128 (float4, coalesced)
#pragma unroll
        for (int l = 0; l < 4; l++) {
            int idx = tid + l * 256;
            int rr = idx >> 5, c4 = idx & 31;
            *(float4*)&Bs[rr][c4 * 4] = *(const float4*)&Bm[(size_t)(k0 + rr) * DIM + c4 * 4];
        }
        __syncthreads();

#pragma unroll
        for (int k = 0; k < 32; k++) {
            unsigned long long a2[4];
#pragma unroll
            for (int i = 0; i < 4; i++) a2[i] = pack2(As[ty * 4 + i][k]);
            unsigned long long b2[4];
#pragma unroll
            for (int j = 0; j < 4; j++)
                b2[j] = *(const unsigned long long*)&Bs[k][tx * 2 + j * 32];
#pragma unroll
            for (int i = 0; i < 4; i++)
#pragma unroll
                for (int j = 0; j < 4; j++) fma2(c2[i][j], a2[i], b2[j]);
        }
        __syncthreads();
    }

    // store
#pragma unroll
    for (int i = 0; i < 4; i++) {
        int gr = row0 + ty * 4 + i;
        if (gr < Nn) {
#pragma unroll
            for (int j = 0; j < 4; j++) {
                int col = tx * 2 + j * 32;
                float lo, hi;
                unpack2(c2[i][j], lo, hi);
                if (z == 8) { lo += bias[col]; hi += bias[col + 1]; }
                float2 v; v.x = lo; v.y = hi;
                *(float2*)&C[(size_t)gr * DIM + col] = v;
            }
        }
    }
}

// ---------------- scatter: acc[t] += Y[r][h] * inv_cnt[r,t]  (one warp per edge) ----------------
__global__ __launch_bounds__(256) void k_scatter(
    const float* __restrict__ Y, const int* __restrict__ h, const int* __restrict__ r,
    const int* __restrict__ t, const float* __restrict__ inv,
    float* __restrict__ acc, int E)
{
    int gw = (blockIdx.x * blockDim.x + threadIdx.x) >> 5;
    int lane = threadIdx.x & 31;
    if (gw >= E) return;
    int hh = h[gw], rr = r[gw], tt = t[gw];
    float w = inv[rr * NNODES + tt];
    const float4* src = (const float4*)(Y + ((size_t)rr * NNODES + hh) * DIM);
    float4 v = src[lane];
    float4* dst = (float4*)(acc + (size_t)tt * DIM) + lane;
    asm volatile("red.global.add.v4.f32 [%0], {%1, %2, %3, %4};"
                 :: "l"(dst), "f"(v.x * w), "f"(v.y * w), "f"(v.z * w), "f"(v.w * w)
                 : "memory");
}

// ---------------- relu (in place, float4) ----------------
__global__ void k_relu(float4* __restrict__ p, int n4) {
    int i = blockIdx.x * blockDim.x + threadIdx.x;
    if (i < n4) {
        float4 v = p[i];
        v.x = fmaxf(v.x, 0.0f); v.y = fmaxf(v.y, 0.0f);
        v.z = fmaxf(v.z, 0.0f); v.w = fmaxf(v.w, 0.0f);
        p[i] = v;
    }
}

// ---------------- final column mean ----------------
__global__ void k_zero_out(float* __restrict__ out) {
    out[threadIdx.x] = 0.0f;
}

__global__ void k_colmean(const float* __restrict__ X, float* __restrict__ out, int Nn) {
    int col = threadIdx.x;  // 128 threads
    float s = 0.0f;
    for (int n = blockIdx.x; n < Nn; n += gridDim.x)
        s += X[(size_t)n * DIM + col];
    atomicAdd(&out[col], s * (1.0f / (float)Nn));
}

// ---------------- launch ----------------
extern "C" void kernel_launch(void* const* d_in, const int* in_sizes, int n_in,
                              void* d_out, int out_size) {
    const int*   h     = (const int*)d_in[0];
    const int*   r     = (const int*)d_in[1];
    const int*   t     = (const int*)d_in[2];
    const float* x_emb = (const float*)d_in[3];
    const float* W1    = (const float*)d_in[4];
    const float* root1 = (const float*)d_in[5];
    const float* b1    = (const float*)d_in[6];
    const float* W2    = (const float*)d_in[7];
    const float* root2 = (const float*)d_in[8];
    const float* b2    = (const float*)d_in[9];
    float* out = (float*)d_out;

    float *Y, *h1, *h2, *inv;
    int* cnt;
    cudaGetSymbolAddress((void**)&Y,   g_Y);
    cudaGetSymbolAddress((void**)&h1,  g_h1);
    cudaGetSymbolAddress((void**)&h2,  g_h2);
    cudaGetSymbolAddress((void**)&inv, g_inv);
    cudaGetSymbolAddress((void**)&cnt, g_cnt);

    const int E = NEDGES;
    const int Nn = NNODES;
    const int SEG = NREL * NNODES;

    // segment counts -> inverse counts (shared by both layers)
    k_zero_cnt<<<(SEG + 255) / 256, 256>>>(cnt, SEG);
    k_count<<<(E + 255) / 256, 256>>>(r, t, cnt, E);
    k_invert<<<(SEG + 255) / 256, 256>>>(cnt, inv, SEG);

    dim3 ggrid((Nn + 63) / 64, 1, 9);
    int scat_blocks = (E * 32 + 255) / 256;

    // ---- layer 1 ----
    k_gemm9<<<ggrid, 256>>>(x_emb, W1, root1, b1, Y, h1, Nn);
    k_scatter<<<scat_blocks, 256>>>(Y, h, r, t, inv, h1, E);
    k_relu<<<(Nn * DIM / 4 + 255) / 256, 256>>>((float4*)h1, Nn * DIM / 4);

    // ---- layer 2 ----
    k_gemm9<<<ggrid, 256>>>(h1, W2, root2, b2, Y, h2, Nn);
    k_scatter<<<scat_blocks, 256>>>(Y, h, r, t, inv, h2, E);

    // ---- final mean over nodes -> [1, 128] ----
    k_zero_out<<<1, DIM>>>(out);
    k_colmean<<<512, DIM>>>(h2, out, Nn);
}

// round 4
// speedup vs baseline: 1.7680x; 1.7680x over previous
#include <cuda_runtime.h>
#include <cstdint>

// Problem constants (fixed by the reference)
#define NNODES 50000
#define NREL   8
#define DIM    128
#define NEDGES 800000
#define NZ     9                       // 8 relations + root path
#define MTILE  128
#define NRB    ((NNODES + MTILE - 1) / MTILE)   // 391 row blocks

#define ASTR 36                        // A smem row stride (floats): (4g+q)%32 == lane, conflict-free
#define BSTR 136                       // B smem row stride (floats): 136%32=8 -> (8q+g)%32 bijective
#define A_TILE_FLOATS (MTILE * ASTR)   // 4608
#define B_TILE_FLOATS (32 * BSTR)      // 4352
#define SMEM_BYTES ((2 * A_TILE_FLOATS + 2 * B_TILE_FLOATS) * 4)  // 71680

// ---------------- scratch (static device globals; no allocation) ----------------
__device__ float g_Y[(size_t)NREL * NNODES * DIM];   // per-relation transformed features
__device__ float g_h1[(size_t)NNODES * DIM];
__device__ float g_h2[(size_t)NNODES * DIM];
__device__ float g_A[(size_t)NNODES * DIM];          // tf32-rounded layer-1 input
__device__ float g_WR[2 * NZ * DIM * DIM];           // tf32-rounded weights [z][k][n], both layers
__device__ float g_inv[NREL * NNODES];
__device__ int   g_cnt[NREL * NNODES];

// ---------------- helpers ----------------
__device__ __forceinline__ float tf32r(float x) {
    uint32_t u;
    asm("cvt.rna.tf32.f32 %0, %1;" : "=r"(u) : "f"(x));
    return __uint_as_float(u);
}
__device__ __forceinline__ void mma_tf32(float* c, const uint32_t* a, const uint32_t* b) {
    asm volatile(
        "mma.sync.aligned.m16n8k8.row.col.f32.tf32.tf32.f32 "
        "{%0,%1,%2,%3}, {%4,%5,%6,%7}, {%8,%9}, {%0,%1,%2,%3};"
        : "+f"(c[0]), "+f"(c[1]), "+f"(c[2]), "+f"(c[3])
        : "r"(a[0]), "r"(a[1]), "r"(a[2]), "r"(a[3]), "r"(b[0]), "r"(b[1]));
}
__device__ __forceinline__ void cp_async16(uint32_t daddr, const void* src, int srcbytes) {
    asm volatile("cp.async.cg.shared.global [%0], [%1], 16, %2;"
                 :: "r"(daddr), "l"(src), "r"(srcbytes));
}
#define CP_COMMIT() asm volatile("cp.async.commit_group;" ::: "memory")
#define CP_WAIT1()  asm volatile("cp.async.wait_group 1;" ::: "memory")
#define CP_WAIT0()  asm volatile("cp.async.wait_group 0;" ::: "memory")

// ---------------- setup kernels ----------------
__global__ void k_zero_cnt(int* __restrict__ cnt, int n) {
    int i = blockIdx.x * blockDim.x + threadIdx.x;
    if (i < n) cnt[i] = 0;
}
__global__ void k_count(const int* __restrict__ r, const int* __restrict__ t,
                        int* __restrict__ cnt, int E) {
    int e = blockIdx.x * blockDim.x + threadIdx.x;
    if (e < E) atomicAdd(&cnt[r[e] * NNODES + t[e]], 1);
}
__global__ void k_invert(const int* __restrict__ cnt, float* __restrict__ inv, int n) {
    int i = blockIdx.x * blockDim.x + threadIdx.x;
    if (i < n) inv[i] = 1.0f / fmaxf((float)cnt[i], 1.0f);
}

// WR[z][k][n] = round_tf32( (z<8 ? W[z] : root)[k][n] )   (no transpose)
__global__ void k_wt(const float* __restrict__ W, const float* __restrict__ root,
                     float* __restrict__ dst) {
    int idx = blockIdx.x * blockDim.x + threadIdx.x;
    if (idx >= NZ * DIM * DIM) return;
    int z = idx >> 14, rem = idx & 16383;
    const float* src = (z < 8) ? (W + ((size_t)z << 14)) : root;
    dst[idx] = tf32r(src[rem]);
}

__global__ void k_round(const float4* __restrict__ in, float4* __restrict__ out, int n4) {
    int i = blockIdx.x * blockDim.x + threadIdx.x;
    if (i < n4) {
        float4 v = in[i];
        v.x = tf32r(v.x); v.y = tf32r(v.y); v.z = tf32r(v.z); v.w = tf32r(v.w);
        out[i] = v;
    }
}

__global__ void k_relu_round(float4* __restrict__ p, int n4) {
    int i = blockIdx.x * blockDim.x + threadIdx.x;
    if (i < n4) {
        float4 v = p[i];
        v.x = tf32r(fmaxf(v.x, 0.0f)); v.y = tf32r(fmaxf(v.y, 0.0f));
        v.z = tf32r(fmaxf(v.z, 0.0f)); v.w = tf32r(fmaxf(v.w, 0.0f));
        p[i] = v;
    }
}

// ---------------- mma.sync tf32 GEMM: C_z = X @ W_z  (W is [K,N] row-major) ----------------
// CTA: 128x128 tile, BK=32, 8 warps in 4x2 (warp_m x warp_n), each warp 32x64.
// cp.async double-buffered over 4 K-chunks. Dynamic smem (71680 B).
__global__ __launch_bounds__(256, 2) void k_gemm_mma(
    const float* __restrict__ X, const float* __restrict__ WR,
    const float* __restrict__ bias, float* __restrict__ Y,
    float* __restrict__ acc, int Nn)
{
    extern __shared__ float smem[];
    float* As0 = smem;                                    // [2][A_TILE_FLOATS]
    float* Bs0 = smem + 2 * A_TILE_FLOATS;                // [2][B_TILE_FLOATS]

    const int tid = threadIdx.x;
    const int wid = tid >> 5;
    const int lane = tid & 31;
    const int g = lane >> 2;         // 0..7
    const int q = lane & 3;          // 0..3
    const int warp_m = wid & 3;      // rows 32*warp_m
    const int warp_n = wid >> 2;     // cols 64*warp_n
    const int z = blockIdx.y;
    const int row0 = blockIdx.x * MTILE;

    const float* Bsrc = WR + ((size_t)z << 14);
    float* C = (z < 8) ? (Y + (size_t)z * Nn * DIM) : acc;

    float cfrag[2][8][4];
#pragma unroll
    for (int mt = 0; mt < 2; mt++)
#pragma unroll
        for (int nt = 0; nt < 8; nt++)
#pragma unroll
            for (int i = 0; i < 4; i++) cfrag[mt][nt][i] = 0.0f;

    // ---- chunk prefetch ----
    // A tile 128x32: lin = tid + 256*l (l=0..3): row = lin>>3, c4 = lin&7
    // B tile 32x128: lin: krow = lin>>5, c4 = lin&31
    auto load_chunk = [&](int buf, int k0) {
        uint32_t abase = (uint32_t)__cvta_generic_to_shared(As0 + buf * A_TILE_FLOATS);
        uint32_t bbase = (uint32_t)__cvta_generic_to_shared(Bs0 + buf * B_TILE_FLOATS);
#pragma unroll
        for (int l = 0; l < 4; l++) {
            int lin = tid + 256 * l;
            int arow = lin >> 3, ac4 = lin & 7;
            int gr = row0 + arow;
            int ok = (gr < Nn) ? 16 : 0;
            int grc = (gr < Nn) ? gr : (Nn - 1);
            cp_async16(abase + (uint32_t)(arow * ASTR + ac4 * 4) * 4,
                       X + (size_t)grc * DIM + k0 + ac4 * 4, ok);
        }
#pragma unroll
        for (int l = 0; l < 4; l++) {
            int lin = tid + 256 * l;
            int krow = lin >> 5, bc4 = lin & 31;
            cp_async16(bbase + (uint32_t)(krow * BSTR + bc4 * 4) * 4,
                       Bsrc + (size_t)(k0 + krow) * DIM + bc4 * 4, 16);
        }
        CP_COMMIT();
    };

    load_chunk(0, 0);

#pragma unroll
    for (int c = 0; c < 4; c++) {
        if (c < 3) load_chunk((c + 1) & 1, (c + 1) * 32);
        if (c < 3) CP_WAIT1(); else CP_WAIT0();
        __syncthreads();

        const float* A_ = As0 + (c & 1) * A_TILE_FLOATS;
        const float* B_ = Bs0 + (c & 1) * B_TILE_FLOATS;
        const int ar = warp_m * 32 + g;
        const int bn = warp_n * 64 + g;

#pragma unroll
        for (int ks = 0; ks < 4; ks++) {
            const int kc = ks * 8 + q;
            uint32_t a[2][4];
#pragma unroll
            for (int mt = 0; mt < 2; mt++) {
                int base = (ar + mt * 16) * ASTR + kc;
                a[mt][0] = __float_as_uint(A_[base]);
                a[mt][1] = __float_as_uint(A_[base + 8 * ASTR]);
                a[mt][2] = __float_as_uint(A_[base + 4]);
                a[mt][3] = __float_as_uint(A_[base + 8 * ASTR + 4]);
            }
            uint32_t b[8][2];
#pragma unroll
            for (int nt = 0; nt < 8; nt++) {
                b[nt][0] = __float_as_uint(B_[kc * BSTR + bn + nt * 8]);
                b[nt][1] = __float_as_uint(B_[(kc + 4) * BSTR + bn + nt * 8]);
            }
#pragma unroll
            for (int mt = 0; mt < 2; mt++)
#pragma unroll
                for (int nt = 0; nt < 8; nt++)
                    mma_tf32(cfrag[mt][nt], a[mt], b[nt]);
        }
        __syncthreads();
    }

    // ---- epilogue ----
#pragma unroll
    for (int mt = 0; mt < 2; mt++) {
#pragma unroll
        for (int half = 0; half < 2; half++) {
            int row = row0 + warp_m * 32 + mt * 16 + half * 8 + g;
            if (row >= Nn) continue;
#pragma unroll
            for (int nt = 0; nt < 8; nt++) {
                int col = warp_n * 64 + nt * 8 + 2 * q;
                float2 v;
                v.x = cfrag[mt][nt][half * 2 + 0];
                v.y = cfrag[mt][nt][half * 2 + 1];
                if (z == 8) { v.x += bias[col]; v.y += bias[col + 1]; }
                *(float2*)&C[(size_t)row * DIM + col] = v;
            }
        }
    }
}

// ---------------- scatter: acc[t] += Y[r][h] * inv_cnt[r,t]  (one warp per edge) ----------------
__global__ __launch_bounds__(256) void k_scatter(
    const float* __restrict__ Y, const int* __restrict__ h, const int* __restrict__ r,
    const int* __restrict__ t, const float* __restrict__ inv,
    float* __restrict__ acc, int E)
{
    int gw = (blockIdx.x * blockDim.x + threadIdx.x) >> 5;
    int lane = threadIdx.x & 31;
    if (gw >= E) return;
    int hh = h[gw], rr = r[gw], tt = t[gw];
    float w = inv[rr * NNODES + tt];
    const float4* src = (const float4*)(Y + ((size_t)rr * NNODES + hh) * DIM);
    float4 v = src[lane];
    float4* dst = (float4*)(acc + (size_t)tt * DIM) + lane;
    asm volatile("red.global.add.v4.f32 [%0], {%1, %2, %3, %4};"
                 :: "l"(dst), "f"(v.x * w), "f"(v.y * w), "f"(v.z * w), "f"(v.w * w)
                 : "memory");
}

// ---------------- final column mean ----------------
__global__ void k_zero_out(float* __restrict__ out) { out[threadIdx.x] = 0.0f; }

__global__ void k_colmean(const float* __restrict__ X, float* __restrict__ out, int Nn) {
    int col = threadIdx.x;
    float s = 0.0f;
    for (int n = blockIdx.x; n < Nn; n += gridDim.x)
        s += X[(size_t)n * DIM + col];
    atomicAdd(&out[col], s * (1.0f / (float)Nn));
}

// ---------------- launch ----------------
extern "C" void kernel_launch(void* const* d_in, const int* in_sizes, int n_in,
                              void* d_out, int out_size) {
    const int*   h     = (const int*)d_in[0];
    const int*   r     = (const int*)d_in[1];
    const int*   t     = (const int*)d_in[2];
    const float* x_emb = (const float*)d_in[3];
    const float* W1    = (const float*)d_in[4];
    const float* root1 = (const float*)d_in[5];
    const float* b1    = (const float*)d_in[6];
    const float* W2    = (const float*)d_in[7];
    const float* root2 = (const float*)d_in[8];
    const float* b2    = (const float*)d_in[9];
    float* out = (float*)d_out;

    float *Y, *h1, *h2, *A, *WR, *inv;
    int* cnt;
    cudaGetSymbolAddress((void**)&Y,   g_Y);
    cudaGetSymbolAddress((void**)&h1,  g_h1);
    cudaGetSymbolAddress((void**)&h2,  g_h2);
    cudaGetSymbolAddress((void**)&A,   g_A);
    cudaGetSymbolAddress((void**)&WR,  g_WR);
    cudaGetSymbolAddress((void**)&inv, g_inv);
    cudaGetSymbolAddress((void**)&cnt, g_cnt);

    const int E = NEDGES, Nn = NNODES, SEG = NREL * NNODES;

    static bool attr_set = false;
    if (!attr_set) {
        cudaFuncSetAttribute(k_gemm_mma, cudaFuncAttributeMaxDynamicSharedMemorySize, SMEM_BYTES);
        attr_set = true;
    }

    // segment counts -> inverse counts
    k_zero_cnt<<<(SEG + 255) / 256, 256>>>(cnt, SEG);
    k_count<<<(E + 255) / 256, 256>>>(r, t, cnt, E);
    k_invert<<<(SEG + 255) / 256, 256>>>(cnt, inv, SEG);

    // weights: tf32 rounding (both layers)
    int wt_blk = (NZ * DIM * DIM + 255) / 256;
    k_wt<<<wt_blk, 256>>>(W1, root1, WR);
    k_wt<<<wt_blk, 256>>>(W2, root2, WR + (size_t)NZ * DIM * DIM);

    // round layer-1 input to tf32
    int n4 = Nn * DIM / 4;
    k_round<<<(n4 + 255) / 256, 256>>>((const float4*)x_emb, (float4*)A, n4);

    dim3 ggrid(NRB, NZ);
    int scat_blocks = (E + 7) / 8;

    // ---- layer 1 ----
    k_gemm_mma<<<ggrid, 256, SMEM_BYTES>>>(A, WR, b1, Y, h1, Nn);
    k_scatter<<<scat_blocks, 256>>>(Y, h, r, t, inv, h1, E);
    k_relu_round<<<(n4 + 255) / 256, 256>>>((float4*)h1, n4);

    // ---- layer 2 ----
    k_gemm_mma<<<ggrid, 256, SMEM_BYTES>>>(h1, WR + (size_t)NZ * DIM * DIM, b2, Y, h2, Nn);
    k_scatter<<<scat_blocks, 256>>>(Y, h, r, t, inv, h2, E);

    // ---- final mean over nodes -> [1, 128] ----
    k_zero_out<<<1, DIM>>>(out);
    k_colmean<<<512, DIM>>>(h2, out, Nn);
}

// round 5
// speedup vs baseline: 2.1681x; 1.2263x over previous
#include <cuda_runtime.h>
#include <cuda_fp16.h>
#include <cstdint>

// Problem constants (fixed by the reference)
#define NNODES 50000
#define NREL   8
#define DIM    128
#define NEDGES 800000
#define NZ     9                       // 8 relations + root path
#define MTILE  128
#define NRB    ((NNODES + MTILE - 1) / MTILE)   // 391 row blocks

// smem tiles are viewed as uint32 (half2). 32 halves/row = 16 u32, padded to 20:
// fragment-load banks (20*g + q) % 32 are a bijection over the warp -> conflict-free.
#define TSTR32 20
#define A_TILE_U32 (MTILE * TSTR32)    // 2560
#define B_TILE_U32 (MTILE * TSTR32)    // 2560 (B stored transposed: 128 n-rows x 32 k-halves)

// ---------------- scratch (static device globals; no allocation) ----------------
__device__ __half g_Y16[(size_t)NREL * NNODES * DIM]; // per-relation transformed features (fp16)
__device__ float  g_h1[(size_t)NNODES * DIM];
__device__ float  g_h2[(size_t)NNODES * DIM];
__device__ __half g_A16[(size_t)NNODES * DIM];        // fp16 GEMM input (layer 1: x_emb, layer 2: relu(h1))
__device__ __half g_WH[2 * NZ * DIM * DIM];           // fp16 transposed weights [z][n][k], both layers
__device__ float  g_inv[NREL * NNODES];
__device__ int    g_cnt[NREL * NNODES];

// ---------------- helpers ----------------
__device__ __forceinline__ void mma_f16(float* c, const uint32_t* a, const uint32_t* b) {
    asm volatile(
        "mma.sync.aligned.m16n8k16.row.col.f32.f16.f16.f32 "
        "{%0,%1,%2,%3}, {%4,%5,%6,%7}, {%8,%9}, {%0,%1,%2,%3};"
        : "+f"(c[0]), "+f"(c[1]), "+f"(c[2]), "+f"(c[3])
        : "r"(a[0]), "r"(a[1]), "r"(a[2]), "r"(a[3]), "r"(b[0]), "r"(b[1]));
}
__device__ __forceinline__ void cp_async16(uint32_t daddr, const void* src, int srcbytes) {
    asm volatile("cp.async.cg.shared.global [%0], [%1], 16, %2;"
                 :: "r"(daddr), "l"(src), "r"(srcbytes));
}
#define CP_COMMIT() asm volatile("cp.async.commit_group;" ::: "memory")
#define CP_WAIT1()  asm volatile("cp.async.wait_group 1;" ::: "memory")
#define CP_WAIT0()  asm volatile("cp.async.wait_group 0;" ::: "memory")

// ---------------- setup kernels ----------------
__global__ void k_zero_cnt(int* __restrict__ cnt, int n) {
    int i = blockIdx.x * blockDim.x + threadIdx.x;
    if (i < n) cnt[i] = 0;
}
__global__ void k_count(const int* __restrict__ r, const int* __restrict__ t,
                        int* __restrict__ cnt, int E) {
    int e = blockIdx.x * blockDim.x + threadIdx.x;
    if (e < E) atomicAdd(&cnt[r[e] * NNODES + t[e]], 1);
}
__global__ void k_invert(const int* __restrict__ cnt, float* __restrict__ inv, int n) {
    int i = blockIdx.x * blockDim.x + threadIdx.x;
    if (i < n) inv[i] = 1.0f / fmaxf((float)cnt[i], 1.0f);
}

// WH[z][n][k] = fp16( (z<8 ? W[z] : root)[k][n] )   (transpose + convert)
__global__ void k_wt(const float* __restrict__ W, const float* __restrict__ root,
                     __half* __restrict__ dst) {
    int idx = blockIdx.x * blockDim.x + threadIdx.x;
    if (idx >= NZ * DIM * DIM) return;
    int z = idx >> 14, rem = idx & 16383;
    int n = rem >> 7, k = rem & 127;
    const float* src = (z < 8) ? (W + ((size_t)z << 14)) : root;
    dst[idx] = __float2half_rn(src[k * DIM + n]);
}

// fp32 -> fp16 (layer-1 input)
__global__ void k_cvt16(const float2* __restrict__ in, uint32_t* __restrict__ out, int n2) {
    int i = blockIdx.x * blockDim.x + threadIdx.x;
    if (i < n2) {
        float2 v = in[i];
        __half2 hv = __floats2half2_rn(v.x, v.y);
        out[i] = *(uint32_t*)&hv;
    }
}

// relu(fp32) -> fp16 (layer-2 input)
__global__ void k_relu16(const float2* __restrict__ in, uint32_t* __restrict__ out, int n2) {
    int i = blockIdx.x * blockDim.x + threadIdx.x;
    if (i < n2) {
        float2 v = in[i];
        __half2 hv = __floats2half2_rn(fmaxf(v.x, 0.0f), fmaxf(v.y, 0.0f));
        out[i] = *(uint32_t*)&hv;
    }
}

// ---------------- fp16 mma.sync GEMM: C_z = X @ W_z ----------------
// CTA: 128x128 tile, BK=32, 8 warps in 4x2 (warp_m x warp_n), each warp 32x64.
// A smem: [128 rows][32 halves] padded; B smem: transposed [128 n][32 k] padded.
// cp.async double-buffered over 4 K-chunks. z<8 -> fp16 Y; z==8 -> fp32 acc + bias.
__global__ __launch_bounds__(256, 2) void k_gemm_mma(
    const __half* __restrict__ X, const __half* __restrict__ WH,
    const float* __restrict__ bias, __half* __restrict__ Y,
    float* __restrict__ acc, int Nn)
{
    __shared__ uint32_t As[2][A_TILE_U32];
    __shared__ uint32_t Bs[2][B_TILE_U32];

    const int tid = threadIdx.x;
    const int wid = tid >> 5;
    const int lane = tid & 31;
    const int g = lane >> 2;         // 0..7
    const int q = lane & 3;          // 0..3
    const int warp_m = wid & 3;      // rows 32*warp_m
    const int warp_n = wid >> 2;     // cols 64*warp_n
    const int z = blockIdx.y;
    const int row0 = blockIdx.x * MTILE;

    const __half* Bsrc = WH + ((size_t)z << 14);

    float cfrag[2][8][4];
#pragma unroll
    for (int mt = 0; mt < 2; mt++)
#pragma unroll
        for (int nt = 0; nt < 8; nt++)
#pragma unroll
            for (int i = 0; i < 4; i++) cfrag[mt][nt][i] = 0.0f;

    // chunk fill: A 128 rows x 64 B, B_T 128 rows x 64 B; 16B cp.async,
    // lin = tid + 256*l: row = lin>>2, seg = lin&3 (seg = 8 halves)
    auto load_chunk = [&](int buf, int k0) {
        uint32_t abase = (uint32_t)__cvta_generic_to_shared(&As[buf][0]);
        uint32_t bbase = (uint32_t)__cvta_generic_to_shared(&Bs[buf][0]);
#pragma unroll
        for (int l = 0; l < 2; l++) {
            int lin = tid + 256 * l;
            int row = lin >> 2, seg = lin & 3;
            int gr = row0 + row;
            int ok = (gr < Nn) ? 16 : 0;
            int grc = (gr < Nn) ? gr : (Nn - 1);
            cp_async16(abase + (uint32_t)(row * TSTR32 + seg * 4) * 4,
                       X + (size_t)grc * DIM + k0 + seg * 8, ok);
        }
#pragma unroll
        for (int l = 0; l < 2; l++) {
            int lin = tid + 256 * l;
            int row = lin >> 2, seg = lin & 3;   // row = n index
            cp_async16(bbase + (uint32_t)(row * TSTR32 + seg * 4) * 4,
                       Bsrc + (size_t)row * DIM + k0 + seg * 8, 16);
        }
        CP_COMMIT();
    };

    load_chunk(0, 0);

#pragma unroll
    for (int c = 0; c < 4; c++) {
        if (c < 3) load_chunk((c + 1) & 1, (c + 1) * 32);
        if (c < 3) CP_WAIT1(); else CP_WAIT0();
        __syncthreads();

        const uint32_t* A_ = As[c & 1];
        const uint32_t* B_ = Bs[c & 1];
        const int ar = warp_m * 32 + g;
        const int bn = warp_n * 64 + g;

#pragma unroll
        for (int ks = 0; ks < 2; ks++) {
            const int ko = ks * 8 + q;           // u32 index within 16-u32 row
            uint32_t a[2][4];
#pragma unroll
            for (int mt = 0; mt < 2; mt++) {
                int base = (ar + mt * 16) * TSTR32 + ko;
                a[mt][0] = A_[base];
                a[mt][1] = A_[base + 8 * TSTR32];
                a[mt][2] = A_[base + 4];
                a[mt][3] = A_[base + 8 * TSTR32 + 4];
            }
            uint32_t b[8][2];
#pragma unroll
            for (int nt = 0; nt < 8; nt++) {
                int base = (bn + nt * 8) * TSTR32 + ko;
                b[nt][0] = B_[base];
                b[nt][1] = B_[base + 4];
            }
#pragma unroll
            for (int mt = 0; mt < 2; mt++)
#pragma unroll
                for (int nt = 0; nt < 8; nt++)
                    mma_f16(cfrag[mt][nt], a[mt], b[nt]);
        }
        __syncthreads();
    }

    // ---- epilogue ----
    if (z < 8) {
        __half* C = Y + (size_t)z * Nn * DIM;
#pragma unroll
        for (int mt = 0; mt < 2; mt++) {
#pragma unroll
            for (int half_ = 0; half_ < 2; half_++) {
                int row = row0 + warp_m * 32 + mt * 16 + half_ * 8 + g;
                if (row >= Nn) continue;
#pragma unroll
                for (int nt = 0; nt < 8; nt++) {
                    int col = warp_n * 64 + nt * 8 + 2 * q;
                    __half2 hv = __floats2half2_rn(cfrag[mt][nt][half_ * 2 + 0],
                                                   cfrag[mt][nt][half_ * 2 + 1]);
                    *(uint32_t*)&C[(size_t)row * DIM + col] = *(uint32_t*)&hv;
                }
            }
        }
    } else {
        float* C = acc;
#pragma unroll
        for (int mt = 0; mt < 2; mt++) {
#pragma unroll
            for (int half_ = 0; half_ < 2; half_++) {
                int row = row0 + warp_m * 32 + mt * 16 + half_ * 8 + g;
                if (row >= Nn) continue;
#pragma unroll
                for (int nt = 0; nt < 8; nt++) {
                    int col = warp_n * 64 + nt * 8 + 2 * q;
                    float2 v;
                    v.x = cfrag[mt][nt][half_ * 2 + 0] + bias[col];
                    v.y = cfrag[mt][nt][half_ * 2 + 1] + bias[col + 1];
                    *(float2*)&C[(size_t)row * DIM + col] = v;
                }
            }
        }
    }
}

// ---------------- scatter: acc[t] += Y16[r][h] * inv_cnt[r,t]  (16 lanes per edge) ----------------
__global__ __launch_bounds__(256) void k_scatter16(
    const __half* __restrict__ Y, const int* __restrict__ h, const int* __restrict__ r,
    const int* __restrict__ t, const float* __restrict__ inv,
    float* __restrict__ acc, int E)
{
    int idx = blockIdx.x * blockDim.x + threadIdx.x;
    int e = idx >> 4;
    int l16 = idx & 15;
    if (e >= E) return;
    int hh = h[e], rr = r[e], tt = t[e];
    float w = inv[rr * NNODES + tt];
    const uint4* src = (const uint4*)(Y + ((size_t)rr * NNODES + hh) * DIM);
    uint4 v = src[l16];                      // 8 halves
    __half2* hp = (__half2*)&v;
    float2 f0 = __half22float2(hp[0]);
    float2 f1 = __half22float2(hp[1]);
    float2 f2 = __half22float2(hp[2]);
    float2 f3 = __half22float2(hp[3]);
    float* dst = acc + (size_t)tt * DIM + l16 * 8;
    asm volatile("red.global.add.v4.f32 [%0], {%1, %2, %3, %4};"
                 :: "l"(dst), "f"(f0.x * w), "f"(f0.y * w), "f"(f1.x * w), "f"(f1.y * w)
                 : "memory");
    asm volatile("red.global.add.v4.f32 [%0], {%1, %2, %3, %4};"
                 :: "l"(dst + 4), "f"(f2.x * w), "f"(f2.y * w), "f"(f3.x * w), "f"(f3.y * w)
                 : "memory");
}

// ---------------- final column mean ----------------
__global__ void k_zero_out(float* __restrict__ out) { out[threadIdx.x] = 0.0f; }

__global__ void k_colmean(const float* __restrict__ X, float* __restrict__ out, int Nn) {
    int col = threadIdx.x;
    float s = 0.0f;
    for (int n = blockIdx.x; n < Nn; n += gridDim.x)
        s += X[(size_t)n * DIM + col];
    atomicAdd(&out[col], s * (1.0f / (float)Nn));
}

// ---------------- launch ----------------
extern "C" void kernel_launch(void* const* d_in, const int* in_sizes, int n_in,
                              void* d_out, int out_size) {
    const int*   h     = (const int*)d_in[0];
    const int*   r     = (const int*)d_in[1];
    const int*   t     = (const int*)d_in[2];
    const float* x_emb = (const float*)d_in[3];
    const float* W1    = (const float*)d_in[4];
    const float* root1 = (const float*)d_in[5];
    const float* b1    = (const float*)d_in[6];
    const float* W2    = (const float*)d_in[7];
    const float* root2 = (const float*)d_in[8];
    const float* b2    = (const float*)d_in[9];
    float* out = (float*)d_out;

    __half *Y16, *A16, *WH;
    float *h1, *h2, *inv;
    int* cnt;
    cudaGetSymbolAddress((void**)&Y16, g_Y16);
    cudaGetSymbolAddress((void**)&h1,  g_h1);
    cudaGetSymbolAddress((void**)&h2,  g_h2);
    cudaGetSymbolAddress((void**)&A16, g_A16);
    cudaGetSymbolAddress((void**)&WH,  g_WH);
    cudaGetSymbolAddress((void**)&inv, g_inv);
    cudaGetSymbolAddress((void**)&cnt, g_cnt);

    const int E = NEDGES, Nn = NNODES, SEG = NREL * NNODES;

    // segment counts -> inverse counts
    k_zero_cnt<<<(SEG + 255) / 256, 256>>>(cnt, SEG);
    k_count<<<(E + 255) / 256, 256>>>(r, t, cnt, E);
    k_invert<<<(SEG + 255) / 256, 256>>>(cnt, inv, SEG);

    // weights: transpose + fp16 (both layers)
    int wt_blk = (NZ * DIM * DIM + 255) / 256;
    k_wt<<<wt_blk, 256>>>(W1, root1, WH);
    k_wt<<<wt_blk, 256>>>(W2, root2, WH + (size_t)NZ * DIM * DIM);

    // layer-1 input -> fp16
    int n2 = Nn * DIM / 2;
    k_cvt16<<<(n2 + 255) / 256, 256>>>((const float2*)x_emb, (uint32_t*)A16, n2);

    dim3 ggrid(NRB, NZ);
    int scat_blocks = (E * 16 + 255) / 256;

    // ---- layer 1 ----
    k_gemm_mma<<<ggrid, 256>>>(A16, WH, b1, Y16, h1, Nn);
    k_scatter16<<<scat_blocks, 256>>>(Y16, h, r, t, inv, h1, E);
    k_relu16<<<(n2 + 255) / 256, 256>>>((const float2*)h1, (uint32_t*)A16, n2);

    // ---- layer 2 ----
    k_gemm_mma<<<ggrid, 256>>>(A16, WH + (size_t)NZ * DIM * DIM, b2, Y16, h2, Nn);
    k_scatter16<<<scat_blocks, 256>>>(Y16, h, r, t, inv, h2, E);

    // ---- final mean over nodes -> [1, 128] ----
    k_zero_out<<<1, DIM>>>(out);
    k_colmean<<<512, DIM>>>(h2, out, Nn);
}

// round 6
// speedup vs baseline: 2.7219x; 1.2554x over previous
#include <cuda_runtime.h>
#include <cuda_fp16.h>
#include <cstdint>

// Problem constants (fixed by the reference)
#define NNODES 50000
#define NREL   8
#define DIM    128
#define NEDGES 800000
#define NZ     9                       // 8 relations + root path
#define MTILE  128
#define NRB    ((NNODES + MTILE - 1) / MTILE)   // 391 row blocks
#define SEG    (NREL * NNODES)         // 400000
#define NSCAN_BLK ((SEG + 511) / 512)  // 782

// smem tiles viewed as uint32 (half2). 16 u32/row padded to 20 -> conflict-free.
#define TSTR32 20
#define A_TILE_U32 (MTILE * TSTR32)
#define B_TILE_U32 (MTILE * TSTR32)

// ---------------- scratch (static device globals; no allocation) ----------------
__device__ __half g_Y16[(size_t)NREL * NNODES * DIM]; // per-relation transformed features (fp16)
__device__ float  g_acc[(size_t)NNODES * DIM];        // root-path fp32 accumulator (both layers)
__device__ float  g_h2[(size_t)NNODES * DIM];         // layer-2 output (for column mean)
__device__ __half g_A16[(size_t)NNODES * DIM];        // fp16 GEMM input
__device__ __half g_WH[2 * NZ * DIM * DIM];           // fp16 transposed weights [z][n][k]
__device__ int    g_cnt[SEG];
__device__ int    g_incl[SEG];                        // per-block inclusive scan temp
__device__ int    g_off[SEG + 1];                     // exclusive segment offsets
__device__ int    g_cursor[SEG];
__device__ int    g_binh[NEDGES];                     // h values binned by segment
__device__ int    g_bsum[1024];                       // block sums for scan

// ---------------- helpers ----------------
__device__ __forceinline__ void mma_f16(float* c, const uint32_t* a, const uint32_t* b) {
    asm volatile(
        "mma.sync.aligned.m16n8k16.row.col.f32.f16.f16.f32 "
        "{%0,%1,%2,%3}, {%4,%5,%6,%7}, {%8,%9}, {%0,%1,%2,%3};"
        : "+f"(c[0]), "+f"(c[1]), "+f"(c[2]), "+f"(c[3])
        : "r"(a[0]), "r"(a[1]), "r"(a[2]), "r"(a[3]), "r"(b[0]), "r"(b[1]));
}
__device__ __forceinline__ void cp_async16(uint32_t daddr, const void* src, int srcbytes) {
    asm volatile("cp.async.cg.shared.global [%0], [%1], 16, %2;"
                 :: "r"(daddr), "l"(src), "r"(srcbytes));
}
#define CP_COMMIT() asm volatile("cp.async.commit_group;" ::: "memory")
#define CP_WAIT1()  asm volatile("cp.async.wait_group 1;" ::: "memory")
#define CP_WAIT0()  asm volatile("cp.async.wait_group 0;" ::: "memory")

// ---------------- setup / binning kernels ----------------
__global__ void k_zero_cnt(int* __restrict__ cnt, int n) {
    int i = blockIdx.x * blockDim.x + threadIdx.x;
    if (i < n) cnt[i] = 0;
}
__global__ void k_count(const int* __restrict__ r, const int* __restrict__ t,
                        int* __restrict__ cnt, int E) {
    int e = blockIdx.x * blockDim.x + threadIdx.x;
    if (e < E) atomicAdd(&cnt[r[e] * NNODES + t[e]], 1);
}

// block-level inclusive scan (512/block)
__global__ void k_scan1(const int* __restrict__ cnt, int* __restrict__ incl,
                        int* __restrict__ bsum, int n) {
    __shared__ int sm[512];
    int tid = threadIdx.x;
    int gid = blockIdx.x * 512 + tid;
    sm[tid] = (gid < n) ? cnt[gid] : 0;
    __syncthreads();
#pragma unroll
    for (int d = 1; d < 512; d <<= 1) {
        int add = (tid >= d) ? sm[tid - d] : 0;
        __syncthreads();
        sm[tid] += add;
        __syncthreads();
    }
    if (gid < n) incl[gid] = sm[tid];
    if (tid == 511) bsum[blockIdx.x] = sm[511];
}
// single-block scan of block sums (nb <= 1024)
__global__ void k_scan2(int* __restrict__ bsum, int nb) {
    __shared__ int sm[1024];
    int tid = threadIdx.x;
    sm[tid] = (tid < nb) ? bsum[tid] : 0;
    __syncthreads();
#pragma unroll
    for (int d = 1; d < 1024; d <<= 1) {
        int add = (tid >= d) ? sm[tid - d] : 0;
        __syncthreads();
        sm[tid] += add;
        __syncthreads();
    }
    if (tid < nb) bsum[tid] = sm[tid];
}
// finalize exclusive offsets + cursor copy
__global__ void k_scan3(const int* __restrict__ cnt, const int* __restrict__ incl,
                        const int* __restrict__ bsum, int* __restrict__ off,
                        int* __restrict__ cursor, int n) {
    int gid = blockIdx.x * 512 + threadIdx.x;
    if (gid >= n) return;
    int base = (blockIdx.x > 0) ? bsum[blockIdx.x - 1] : 0;
    int ex = base + incl[gid] - cnt[gid];
    off[gid] = ex;
    cursor[gid] = ex;
    if (gid == n - 1) off[n] = base + incl[gid];
}
// bin each edge's source node by (r,t) segment
__global__ void k_bin(const int* __restrict__ h, const int* __restrict__ r,
                      const int* __restrict__ t, int* __restrict__ cursor,
                      int* __restrict__ binh, int E) {
    int e = blockIdx.x * blockDim.x + threadIdx.x;
    if (e >= E) return;
    int seg = r[e] * NNODES + t[e];
    int pos = atomicAdd(&cursor[seg], 1);
    binh[pos] = h[e];
}

// WH[z][n][k] = fp16( (z<8 ? W[z] : root)[k][n] )
__global__ void k_wt(const float* __restrict__ W, const float* __restrict__ root,
                     __half* __restrict__ dst) {
    int idx = blockIdx.x * blockDim.x + threadIdx.x;
    if (idx >= NZ * DIM * DIM) return;
    int z = idx >> 14, rem = idx & 16383;
    int n = rem >> 7, k = rem & 127;
    const float* src = (z < 8) ? (W + ((size_t)z << 14)) : root;
    dst[idx] = __float2half_rn(src[k * DIM + n]);
}

__global__ void k_cvt16(const float2* __restrict__ in, uint32_t* __restrict__ out, int n2) {
    int i = blockIdx.x * blockDim.x + threadIdx.x;
    if (i < n2) {
        float2 v = in[i];
        __half2 hv = __floats2half2_rn(v.x, v.y);
        out[i] = *(uint32_t*)&hv;
    }
}

// ---------------- fp16 mma.sync GEMM: Y_z = X @ W_z, z==8 -> fp32 acc + bias ----------------
__global__ __launch_bounds__(256, 2) void k_gemm_mma(
    const __half* __restrict__ X, const __half* __restrict__ WH,
    const float* __restrict__ bias, __half* __restrict__ Y,
    float* __restrict__ acc, int Nn)
{
    __shared__ uint32_t As[2][A_TILE_U32];
    __shared__ uint32_t Bs[2][B_TILE_U32];

    const int tid = threadIdx.x;
    const int wid = tid >> 5;
    const int lane = tid & 31;
    const int g = lane >> 2;
    const int q = lane & 3;
    const int warp_m = wid & 3;
    const int warp_n = wid >> 2;
    const int z = blockIdx.y;
    const int row0 = blockIdx.x * MTILE;

    const __half* Bsrc = WH + ((size_t)z << 14);

    float cfrag[2][8][4];
#pragma unroll
    for (int mt = 0; mt < 2; mt++)
#pragma unroll
        for (int nt = 0; nt < 8; nt++)
#pragma unroll
            for (int i = 0; i < 4; i++) cfrag[mt][nt][i] = 0.0f;

    auto load_chunk = [&](int buf, int k0) {
        uint32_t abase = (uint32_t)__cvta_generic_to_shared(&As[buf][0]);
        uint32_t bbase = (uint32_t)__cvta_generic_to_shared(&Bs[buf][0]);
#pragma unroll
        for (int l = 0; l < 2; l++) {
            int lin = tid + 256 * l;
            int row = lin >> 2, seg = lin & 3;
            int gr = row0 + row;
            int ok = (gr < Nn) ? 16 : 0;
            int grc = (gr < Nn) ? gr : (Nn - 1);
            cp_async16(abase + (uint32_t)(row * TSTR32 + seg * 4) * 4,
                       X + (size_t)grc * DIM + k0 + seg * 8, ok);
        }
#pragma unroll
        for (int l = 0; l < 2; l++) {
            int lin = tid + 256 * l;
            int row = lin >> 2, seg = lin & 3;
            cp_async16(bbase + (uint32_t)(row * TSTR32 + seg * 4) * 4,
                       Bsrc + (size_t)row * DIM + k0 + seg * 8, 16);
        }
        CP_COMMIT();
    };

    load_chunk(0, 0);

#pragma unroll
    for (int c = 0; c < 4; c++) {
        if (c < 3) load_chunk((c + 1) & 1, (c + 1) * 32);
        if (c < 3) CP_WAIT1(); else CP_WAIT0();
        __syncthreads();

        const uint32_t* A_ = As[c & 1];
        const uint32_t* B_ = Bs[c & 1];
        const int ar = warp_m * 32 + g;
        const int bn = warp_n * 64 + g;

#pragma unroll
        for (int ks = 0; ks < 2; ks++) {
            const int ko = ks * 8 + q;
            uint32_t a[2][4];
#pragma unroll
            for (int mt = 0; mt < 2; mt++) {
                int base = (ar + mt * 16) * TSTR32 + ko;
                a[mt][0] = A_[base];
                a[mt][1] = A_[base + 8 * TSTR32];
                a[mt][2] = A_[base + 4];
                a[mt][3] = A_[base + 8 * TSTR32 + 4];
            }
            uint32_t b[8][2];
#pragma unroll
            for (int nt = 0; nt < 8; nt++) {
                int base = (bn + nt * 8) * TSTR32 + ko;
                b[nt][0] = B_[base];
                b[nt][1] = B_[base + 4];
            }
#pragma unroll
            for (int mt = 0; mt < 2; mt++)
#pragma unroll
                for (int nt = 0; nt < 8; nt++)
                    mma_f16(cfrag[mt][nt], a[mt], b[nt]);
        }
        __syncthreads();
    }

    if (z < 8) {
        __half* C = Y + (size_t)z * Nn * DIM;
#pragma unroll
        for (int mt = 0; mt < 2; mt++)
#pragma unroll
            for (int half_ = 0; half_ < 2; half_++) {
                int row = row0 + warp_m * 32 + mt * 16 + half_ * 8 + g;
                if (row >= Nn) continue;
#pragma unroll
                for (int nt = 0; nt < 8; nt++) {
                    int col = warp_n * 64 + nt * 8 + 2 * q;
                    __half2 hv = __floats2half2_rn(cfrag[mt][nt][half_ * 2 + 0],
                                                   cfrag[mt][nt][half_ * 2 + 1]);
                    *(uint32_t*)&C[(size_t)row * DIM + col] = *(uint32_t*)&hv;
                }
            }
    } else {
#pragma unroll
        for (int mt = 0; mt < 2; mt++)
#pragma unroll
            for (int half_ = 0; half_ < 2; half_++) {
                int row = row0 + warp_m * 32 + mt * 16 + half_ * 8 + g;
                if (row >= Nn) continue;
#pragma unroll
                for (int nt = 0; nt < 8; nt++) {
                    int col = warp_n * 64 + nt * 8 + 2 * q;
                    float2 v;
                    v.x = cfrag[mt][nt][half_ * 2 + 0] + bias[col];
                    v.y = cfrag[mt][nt][half_ * 2 + 1] + bias[col + 1];
                    *(float2*)&acc[(size_t)row * DIM + col] = v;
                }
            }
    }
}

// ---------------- aggregation: one warp per target node, atomic-free ----------------
// out[t] = acc[t] + sum_r mean_{edges in (r,t)} Y16[r][binh]; MODE 0: relu->fp16 A16,
// MODE 1: fp32 h2.
template <int MODE>
__global__ __launch_bounds__(256) void k_agg(
    const __half* __restrict__ Y, const int* __restrict__ off,
    const int* __restrict__ binh, const float* __restrict__ accin,
    uint32_t* __restrict__ out16, float* __restrict__ out32)
{
    int warp = (blockIdx.x * 256 + threadIdx.x) >> 5;
    int lane = threadIdx.x & 31;
    if (warp >= NNODES) return;
    const int t = warp;

    float4 a4 = ((const float4*)(accin + (size_t)t * DIM))[lane];

#pragma unroll
    for (int rr = 0; rr < NREL; rr++) {
        int seg = rr * NNODES + t;
        int s = __ldg(&off[seg]);
        int e = __ldg(&off[seg + 1]);
        if (e > s) {
            float4 sum = make_float4(0.f, 0.f, 0.f, 0.f);
            const __half* Yr = Y + ((size_t)rr * NNODES) * DIM;
            for (int i = s; i < e; i++) {
                int hh = __ldg(&binh[i]);
                uint2 v = ((const uint2*)(Yr + (size_t)hh * DIM))[lane];
                __half2* hp = (__half2*)&v;
                float2 f0 = __half22float2(hp[0]);
                float2 f1 = __half22float2(hp[1]);
                sum.x += f0.x; sum.y += f0.y; sum.z += f1.x; sum.w += f1.y;
            }
            float w = 1.0f / (float)(e - s);
            a4.x += sum.x * w; a4.y += sum.y * w;
            a4.z += sum.z * w; a4.w += sum.w * w;
        }
    }

    if (MODE == 0) {
        __half2 h0 = __floats2half2_rn(fmaxf(a4.x, 0.f), fmaxf(a4.y, 0.f));
        __half2 h1 = __floats2half2_rn(fmaxf(a4.z, 0.f), fmaxf(a4.w, 0.f));
        uint2 o;
        o.x = *(uint32_t*)&h0;
        o.y = *(uint32_t*)&h1;
        ((uint2*)(out16 + (size_t)t * (DIM / 2)))[lane] = o;
    } else {
        ((float4*)(out32 + (size_t)t * DIM))[lane] = a4;
    }
}

// ---------------- final column mean ----------------
__global__ void k_zero_out(float* __restrict__ out) { out[threadIdx.x] = 0.0f; }

__global__ void k_colmean(const float* __restrict__ X, float* __restrict__ out, int Nn) {
    int col = threadIdx.x;
    float s = 0.0f;
    for (int n = blockIdx.x; n < Nn; n += gridDim.x)
        s += X[(size_t)n * DIM + col];
    atomicAdd(&out[col], s * (1.0f / (float)Nn));
}

// ---------------- launch ----------------
extern "C" void kernel_launch(void* const* d_in, const int* in_sizes, int n_in,
                              void* d_out, int out_size) {
    const int*   h     = (const int*)d_in[0];
    const int*   r     = (const int*)d_in[1];
    const int*   t     = (const int*)d_in[2];
    const float* x_emb = (const float*)d_in[3];
    const float* W1    = (const float*)d_in[4];
    const float* root1 = (const float*)d_in[5];
    const float* b1    = (const float*)d_in[6];
    const float* W2    = (const float*)d_in[7];
    const float* root2 = (const float*)d_in[8];
    const float* b2    = (const float*)d_in[9];
    float* out = (float*)d_out;

    __half *Y16, *A16, *WH;
    float *acc, *h2;
    int *cnt, *incl, *off, *cursor, *binh, *bsum;
    cudaGetSymbolAddress((void**)&Y16,    g_Y16);
    cudaGetSymbolAddress((void**)&acc,    g_acc);
    cudaGetSymbolAddress((void**)&h2,     g_h2);
    cudaGetSymbolAddress((void**)&A16,    g_A16);
    cudaGetSymbolAddress((void**)&WH,     g_WH);
    cudaGetSymbolAddress((void**)&cnt,    g_cnt);
    cudaGetSymbolAddress((void**)&incl,   g_incl);
    cudaGetSymbolAddress((void**)&off,    g_off);
    cudaGetSymbolAddress((void**)&cursor, g_cursor);
    cudaGetSymbolAddress((void**)&binh,   g_binh);
    cudaGetSymbolAddress((void**)&bsum,   g_bsum);

    const int E = NEDGES, Nn = NNODES;

    // ---- CSR build (shared by both layers) ----
    k_zero_cnt<<<(SEG + 255) / 256, 256>>>(cnt, SEG);
    k_count<<<(E + 255) / 256, 256>>>(r, t, cnt, E);
    k_scan1<<<NSCAN_BLK, 512>>>(cnt, incl, bsum, SEG);
    k_scan2<<<1, 1024>>>(bsum, NSCAN_BLK);
    k_scan3<<<NSCAN_BLK, 512>>>(cnt, incl, bsum, off, cursor, SEG);
    k_bin<<<(E + 255) / 256, 256>>>(h, r, t, cursor, binh, E);

    // ---- weights + input conversion ----
    int wt_blk = (NZ * DIM * DIM + 255) / 256;
    k_wt<<<wt_blk, 256>>>(W1, root1, WH);
    k_wt<<<wt_blk, 256>>>(W2, root2, WH + (size_t)NZ * DIM * DIM);
    int n2 = Nn * DIM / 2;
    k_cvt16<<<(n2 + 255) / 256, 256>>>((const float2*)x_emb, (uint32_t*)A16, n2);

    dim3 ggrid(NRB, NZ);
    int agg_blocks = (Nn * 32 + 255) / 256;

    // ---- layer 1 ----
    k_gemm_mma<<<ggrid, 256>>>(A16, WH, b1, Y16, acc, Nn);
    k_agg<0><<<agg_blocks, 256>>>(Y16, off, binh, acc, (uint32_t*)A16, nullptr);

    // ---- layer 2 ----
    k_gemm_mma<<<ggrid, 256>>>(A16, WH + (size_t)NZ * DIM * DIM, b2, Y16, acc, Nn);
    k_agg<1><<<agg_blocks, 256>>>(Y16, off, binh, acc, nullptr, h2);

    // ---- final mean over nodes -> [1, 128] ----
    k_zero_out<<<1, DIM>>>(out);
    k_colmean<<<512, DIM>>>(h2, out, Nn);
}